// round 1
// baseline (speedup 1.0000x reference)
#include <cuda_runtime.h>
#include <math.h>

#define NV       2000000
#define NGROUPS  (NV/4)                 // 500000 groups of 4 vertices
#define BLOCK    256
#define NB       ((NGROUPS + BLOCK - 1) / BLOCK)   // 1954
#define TSTEPS   240

#define D_DT     (1.0/600.0)
#define D_COS_S  0.93969262078590838405
#define D_SIN_S  0.34202014332566871291
#define D_NX     (-D_SIN_S)
#define D_NY     (D_COS_S)
#define D_THR    (-D_COS_S * 0.1)       // -cos(slope)*INIT_HEIGHT
#define D_EPS    1e-6
#define D_INVM   (1.0/(double)NV)

// ---------------- device state ----------------
__device__ double  g_I6[6];                  // sums: xx,yy,zz,xy,xz,yz of r=x-mc
__device__ double  g_inertia[9];             // body-frame inertia (row-major)
__device__ double  g_trans[3], g_quat[4], g_v[3], g_omega[3];
__device__ double  g_mc[3];
__device__ double  g_kn, g_mu, g_ld, g_ad;
__device__ float   g_A[4];                   // A.xyz, thrA  (mask: x·A < thrA)
__device__ float   g_B[4];                   // B.xyz, thrB  (mask: x·B < thrB)
__device__ float   g_sum[3];
__device__ int     g_cnt;
__device__ unsigned g_ticket;

// ---------------- small math helpers ----------------
__device__ __forceinline__ void quat_to_mat(const double* q, double R[3][3]) {
    double n = sqrt(q[0]*q[0] + q[1]*q[1] + q[2]*q[2] + q[3]*q[3]);
    double w = q[0]/n, x = q[1]/n, y = q[2]/n, z = q[3]/n;
    R[0][0] = 1.0 - 2.0*(y*y + z*z); R[0][1] = 2.0*(x*y - w*z);       R[0][2] = 2.0*(x*z + w*y);
    R[1][0] = 2.0*(x*y + w*z);       R[1][1] = 1.0 - 2.0*(x*x + z*z); R[1][2] = 2.0*(y*z - w*x);
    R[2][0] = 2.0*(x*z - w*y);       R[2][1] = 2.0*(y*z + w*x);       R[2][2] = 1.0 - 2.0*(x*x + y*y);
}

__device__ __forceinline__ void inv3(const double m[3][3], double o[3][3]) {
    double c00 = m[1][1]*m[2][2] - m[1][2]*m[2][1];
    double c01 = m[1][2]*m[2][0] - m[1][0]*m[2][2];
    double c02 = m[1][0]*m[2][1] - m[1][1]*m[2][0];
    double det = m[0][0]*c00 + m[0][1]*c01 + m[0][2]*c02;
    double id = 1.0/det;
    o[0][0] = c00*id;
    o[0][1] = (m[0][2]*m[2][1] - m[0][1]*m[2][2])*id;
    o[0][2] = (m[0][1]*m[1][2] - m[0][2]*m[1][1])*id;
    o[1][0] = c01*id;
    o[1][1] = (m[0][0]*m[2][2] - m[0][2]*m[2][0])*id;
    o[1][2] = (m[0][2]*m[1][0] - m[0][0]*m[1][2])*id;
    o[2][0] = c02*id;
    o[2][1] = (m[0][1]*m[2][0] - m[0][0]*m[2][1])*id;
    o[2][2] = (m[0][0]*m[1][1] - m[0][1]*m[1][0])*id;
}

__device__ __forceinline__ void mm3(const double a[3][3], const double b[3][3], double c[3][3]) {
    #pragma unroll
    for (int i = 0; i < 3; i++)
        #pragma unroll
        for (int j = 0; j < 3; j++)
            c[i][j] = a[i][0]*b[0][j] + a[i][1]*b[1][j] + a[i][2]*b[2][j];
}

// per-step reduction constants from current state
__device__ void compute_constants() {
    double R[3][3];
    quat_to_mat(g_quat, R);
    // A = R^T n  (n = (NX, NY, 0))
    double Ax = R[0][0]*D_NX + R[1][0]*D_NY;
    double Ay = R[0][1]*D_NX + R[1][1]*D_NY;
    double Az = R[0][2]*D_NX + R[1][2]*D_NY;
    double thrA = D_THR - ((g_trans[0] + g_mc[0])*D_NX + (g_trans[1] + g_mc[1])*D_NY);
    // n x omega
    double wx = g_omega[0], wy = g_omega[1], wz = g_omega[2];
    double cx =  D_NY*wz;
    double cy = -D_NX*wz;
    double cz =  D_NX*wy - D_NY*wx;
    double Bx = R[0][0]*cx + R[1][0]*cy + R[2][0]*cz;
    double By = R[0][1]*cx + R[1][1]*cy + R[2][1]*cz;
    double Bz = R[0][2]*cx + R[1][2]*cy + R[2][2]*cz;
    double thrB = -(g_v[0]*D_NX + g_v[1]*D_NY);
    g_A[0] = (float)Ax; g_A[1] = (float)Ay; g_A[2] = (float)Az; g_A[3] = (float)thrA;
    g_B[0] = (float)Bx; g_B[1] = (float)By; g_B[2] = (float)Bz; g_B[3] = (float)thrB;
}

// ---------------- kernels ----------------
__global__ void zero_kernel() {
    if (threadIdx.x == 0) {
        #pragma unroll
        for (int i = 0; i < 6; i++) g_I6[i] = 0.0;
        g_sum[0] = g_sum[1] = g_sum[2] = 0.0f;
        g_cnt = 0;
        g_ticket = 0u;
    }
}

__global__ void inertia_kernel(const float* __restrict__ x, const float* __restrict__ mc) {
    double mcx = mc[0], mcy = mc[1], mcz = mc[2];
    double s[6] = {0, 0, 0, 0, 0, 0};
    const float4* p = (const float4*)x;
    for (int g = blockIdx.x*blockDim.x + threadIdx.x; g < NGROUPS; g += gridDim.x*blockDim.x) {
        float4 f0 = p[3*g], f1 = p[3*g + 1], f2 = p[3*g + 2];
        double vx, vy, vz;
        #define ACC(a,b,c) { vx = (double)(a)-mcx; vy = (double)(b)-mcy; vz = (double)(c)-mcz; \
            s[0] += vx*vx; s[1] += vy*vy; s[2] += vz*vz; s[3] += vx*vy; s[4] += vx*vz; s[5] += vy*vz; }
        ACC(f0.x, f0.y, f0.z)
        ACC(f0.w, f1.x, f1.y)
        ACC(f1.z, f1.w, f2.x)
        ACC(f2.y, f2.z, f2.w)
        #undef ACC
    }
    #pragma unroll
    for (int o = 16; o; o >>= 1)
        #pragma unroll
        for (int i = 0; i < 6; i++) s[i] += __shfl_down_sync(0xffffffffu, s[i], o);
    __shared__ double sm[6][BLOCK/32];
    int lane = threadIdx.x & 31, w = threadIdx.x >> 5;
    if (lane == 0)
        #pragma unroll
        for (int i = 0; i < 6; i++) sm[i][w] = s[i];
    __syncthreads();
    if (threadIdx.x == 0) {
        #pragma unroll
        for (int i = 0; i < 6; i++) {
            double t = 0;
            #pragma unroll
            for (int j = 0; j < BLOCK/32; j++) t += sm[i][j];
            atomicAdd(&g_I6[i], t);
        }
    }
}

__global__ void init_kernel(const float* mc, const float* it, const float* iq,
                            const float* iv, const float* kn, const float* mu,
                            const float* ld, const float* ad) {
    double xx = g_I6[0], yy = g_I6[1], zz = g_I6[2];
    double xy = g_I6[3], xz = g_I6[4], yz = g_I6[5];
    double tr = xx + yy + zz;
    g_inertia[0] = tr - xx; g_inertia[4] = tr - yy; g_inertia[8] = tr - zz;
    g_inertia[1] = -xy; g_inertia[3] = -xy;
    g_inertia[2] = -xz; g_inertia[6] = -xz;
    g_inertia[5] = -yz; g_inertia[7] = -yz;
    for (int i = 0; i < 3; i++) {
        g_mc[i]    = (double)mc[i];
        g_trans[i] = (double)it[i];
        g_v[i]     = (double)iv[i];
        g_omega[i] = 0.0;
    }
    double q0 = iq[0], q1 = iq[1], q2 = iq[2], q3 = iq[3];
    double qn = sqrt(q0*q0 + q1*q1 + q2*q2 + q3*q3);
    g_quat[0] = q0/qn; g_quat[1] = q1/qn; g_quat[2] = q2/qn; g_quat[3] = q3/qn;
    g_kn = (double)kn[0]; g_mu = (double)mu[0];
    g_ld = (double)ld[0]; g_ad = (double)ad[0];
    g_sum[0] = g_sum[1] = g_sum[2] = 0.0f;
    g_cnt = 0;
    g_ticket = 0u;
    compute_constants();
}

__device__ void do_update(int t, float* __restrict__ out) {
    int num  = atomicAdd(&g_cnt, 0);
    double s0 = (double)atomicAdd(&g_sum[0], 0.0f);
    double s1 = (double)atomicAdd(&g_sum[1], 0.0f);
    double s2 = (double)atomicAdd(&g_sum[2], 0.0f);

    double numf = (num > 0) ? (double)num : 1.0;
    double ri0 = s0/numf, ri1 = s1/numf, ri2 = s2/numf;

    double R[3][3];
    quat_to_mat(g_quat, R);
    double Ri0 = R[0][0]*ri0 + R[0][1]*ri1 + R[0][2]*ri2;
    double Ri1 = R[1][0]*ri0 + R[1][1]*ri1 + R[1][2]*ri2;
    double Ri2 = R[2][0]*ri0 + R[2][1]*ri1 + R[2][2]*ri2;

    double vx = g_v[0], vy = g_v[1], vz = g_v[2];
    double wx = g_omega[0], wy = g_omega[1], wz = g_omega[2];

    // vi = v + omega x Ri
    double vix = vx + (wy*Ri2 - wz*Ri1);
    double viy = vy + (wz*Ri0 - wx*Ri2);
    double viz = vz + (wx*Ri1 - wy*Ri0);

    double vns = vix*D_NX + viy*D_NY;         // n.z == 0
    double vnx = vns*D_NX, vny = vns*D_NY;    // v_n
    double vtx = vix - vnx, vty = viy - vny, vtz = viz;
    double nvn = fabs(vns);
    double nvt = sqrt(vtx*vtx + vty*vty + vtz*vtz);
    double alpha = 1.0 - g_mu*(1.0 + g_kn)*(nvn/(nvt + D_EPS));
    if (alpha < 0.0) alpha = 0.0;
    // rhs = vi_new - vi, vi_new = -kn*v_n + alpha*v_t
    double rx = (-g_kn*vnx + alpha*vtx) - vix;
    double ry = (-g_kn*vny + alpha*vty) - viy;
    double rz = (          alpha*vtz) - viz;

    // I = R * inertia * R^T
    double In[3][3] = {{g_inertia[0], g_inertia[1], g_inertia[2]},
                       {g_inertia[3], g_inertia[4], g_inertia[5]},
                       {g_inertia[6], g_inertia[7], g_inertia[8]}};
    double Tm[3][3], Rt[3][3], Iw[3][3];
    mm3(R, In, Tm);
    #pragma unroll
    for (int i = 0; i < 3; i++)
        #pragma unroll
        for (int j = 0; j < 3; j++) Rt[i][j] = R[j][i];
    mm3(Tm, Rt, Iw);
    double Iinv[3][3];
    inv3(Iw, Iinv);

    double C[3][3] = {{0.0, -Ri2, Ri1}, {Ri2, 0.0, -Ri0}, {-Ri1, Ri0, 0.0}};
    double U[3][3], M[3][3];
    mm3(C, Iinv, U);
    mm3(U, C, M);
    double K[3][3];
    #pragma unroll
    for (int i = 0; i < 3; i++)
        #pragma unroll
        for (int j = 0; j < 3; j++) K[i][j] = ((i == j) ? D_INVM : 0.0) - M[i][j];
    double Kinv[3][3];
    inv3(K, Kinv);

    double Jx = Kinv[0][0]*rx + Kinv[0][1]*ry + Kinv[0][2]*rz;
    double Jy = Kinv[1][0]*rx + Kinv[1][1]*ry + Kinv[1][2]*rz;
    double Jz = Kinv[2][0]*rx + Kinv[2][1]*ry + Kinv[2][2]*rz;

    bool hit = (num > 0);
    double dvx = hit ? Jx*D_INVM : 0.0;
    double dvy = hit ? Jy*D_INVM : 0.0;
    double dvz = hit ? Jz*D_INVM : 0.0;
    // C*J = Ri x J
    double cjx = Ri1*Jz - Ri2*Jy;
    double cjy = Ri2*Jx - Ri0*Jz;
    double cjz = Ri0*Jy - Ri1*Jx;
    double dwx = hit ? (Iinv[0][0]*cjx + Iinv[0][1]*cjy + Iinv[0][2]*cjz) : 0.0;
    double dwy = hit ? (Iinv[1][0]*cjx + Iinv[1][1]*cjy + Iinv[1][2]*cjz) : 0.0;
    double dwz = hit ? (Iinv[2][0]*cjx + Iinv[2][1]*cjy + Iinv[2][2]*cjz) : 0.0;

    vx = vx*g_ld + dvx;
    vy = (vy - 9.8*D_DT)*g_ld + dvy;
    vz = vz*g_ld + dvz;
    wx = wx*g_ad + dwx;
    wy = wy*g_ad + dwy;
    wz = wz*g_ad + dwz;

    double tx = g_trans[0] + D_DT*vx;
    double ty = g_trans[1] + D_DT*vy;
    double tz = g_trans[2] + D_DT*vz;

    double h = 0.5*D_DT;
    double x1 = wx*h, y1 = wy*h, z1 = wz*h;
    double qw = g_quat[0], qx = g_quat[1], qy = g_quat[2], qz = g_quat[3];
    double nqw = qw + (-x1*qx - y1*qy - z1*qz);
    double nqx = qx + ( x1*qw + y1*qz - z1*qy);
    double nqy = qy + ( y1*qw + z1*qx - x1*qz);
    double nqz = qz + ( z1*qw + x1*qy - y1*qx);
    double qn = sqrt(nqw*nqw + nqx*nqx + nqy*nqy + nqz*nqz);
    nqw /= qn; nqx /= qn; nqy /= qn; nqz /= qn;

    g_trans[0] = tx; g_trans[1] = ty; g_trans[2] = tz;
    g_quat[0] = nqw; g_quat[1] = nqx; g_quat[2] = nqy; g_quat[3] = nqz;
    g_v[0] = vx; g_v[1] = vy; g_v[2] = vz;
    g_omega[0] = wx; g_omega[1] = wy; g_omega[2] = wz;

    out[7*t + 0] = (float)tx;
    out[7*t + 1] = (float)ty;
    out[7*t + 2] = (float)tz;
    out[7*t + 3] = (float)nqw;
    out[7*t + 4] = (float)nqx;
    out[7*t + 5] = (float)nqy;
    out[7*t + 6] = (float)nqz;

    // reset accumulators for next step; compute next-step constants
    g_sum[0] = g_sum[1] = g_sum[2] = 0.0f;
    g_cnt = 0;
    compute_constants();
}

__global__ void __launch_bounds__(BLOCK) step_kernel(const float* __restrict__ x,
                                                     float* __restrict__ out, int t) {
    const float Ax = g_A[0], Ay = g_A[1], Az = g_A[2], thrA = g_A[3];
    const float Bx = g_B[0], By = g_B[1], Bz = g_B[2], thrB = g_B[3];

    int tid = blockIdx.x*blockDim.x + threadIdx.x;
    float sx = 0.0f, sy = 0.0f, sz = 0.0f;
    int c = 0;

    if (tid < NGROUPS) {
        const float4* p = (const float4*)x;
        float4 f0 = p[3*tid], f1 = p[3*tid + 1], f2 = p[3*tid + 2];
        #define PROC(a,b,cc) { float pa = (a)*Ax + (b)*Ay + (cc)*Az; \
                               float pb = (a)*Bx + (b)*By + (cc)*Bz; \
                               if (pa < thrA && pb < thrB) { c++; sx += (a); sy += (b); sz += (cc); } }
        PROC(f0.x, f0.y, f0.z)
        PROC(f0.w, f1.x, f1.y)
        PROC(f1.z, f1.w, f2.x)
        PROC(f2.y, f2.z, f2.w)
        #undef PROC
    }

    // warp reduce
    #pragma unroll
    for (int o = 16; o; o >>= 1) {
        sx += __shfl_down_sync(0xffffffffu, sx, o);
        sy += __shfl_down_sync(0xffffffffu, sy, o);
        sz += __shfl_down_sync(0xffffffffu, sz, o);
        c  += __shfl_down_sync(0xffffffffu, c,  o);
    }
    __shared__ float ssx[BLOCK/32], ssy[BLOCK/32], ssz[BLOCK/32];
    __shared__ int   sc[BLOCK/32];
    int lane = threadIdx.x & 31, w = threadIdx.x >> 5;
    if (lane == 0) { ssx[w] = sx; ssy[w] = sy; ssz[w] = sz; sc[w] = c; }
    __syncthreads();
    if (threadIdx.x == 0) {
        float bx = 0, by = 0, bz = 0; int bc = 0;
        #pragma unroll
        for (int j = 0; j < BLOCK/32; j++) { bx += ssx[j]; by += ssy[j]; bz += ssz[j]; bc += sc[j]; }
        if (bc) {
            atomicAdd(&g_sum[0], bx);
            atomicAdd(&g_sum[1], by);
            atomicAdd(&g_sum[2], bz);
            atomicAdd(&g_cnt, bc);
        }
    }

    // last-block pattern
    __shared__ bool is_last;
    __threadfence();
    if (threadIdx.x == 0) {
        unsigned tk = atomicInc(&g_ticket, NB - 1);   // wraps to 0 when old == NB-1
        is_last = (tk == NB - 1);
    }
    __syncthreads();
    if (is_last && threadIdx.x == 0) {
        do_update(t, out);
    }
}

extern "C" void kernel_launch(void* const* d_in, const int* in_sizes, int n_in,
                              void* d_out, int out_size) {
    const float* x  = (const float*)d_in[0];
    const float* mc = (const float*)d_in[1];
    const float* it = (const float*)d_in[2];
    const float* iq = (const float*)d_in[3];
    const float* iv = (const float*)d_in[4];
    const float* kn = (const float*)d_in[5];
    const float* mu = (const float*)d_in[6];
    const float* ld = (const float*)d_in[7];
    const float* ad = (const float*)d_in[8];
    float* out = (float*)d_out;

    zero_kernel<<<1, 32>>>();
    inertia_kernel<<<1184, BLOCK>>>(x, mc);
    init_kernel<<<1, 1>>>(mc, it, iq, iv, kn, mu, ld, ad);
    for (int t = 0; t < TSTEPS; t++) {
        step_kernel<<<NB, BLOCK>>>(x, out, t);
    }
}

// round 2
// speedup vs baseline: 1.2282x; 1.2282x over previous
#include <cuda_runtime.h>
#include <math.h>

#define NV       2000000
#define NGROUPS  (NV/4)                 // 500000 groups of 4 vertices
#define BLOCK    256
#define NBP      296                    // persistent grid: 2 blocks/SM x 148 SMs
#define TSTEPS   240

#define D_DT     (1.0/600.0)
#define D_COS_S  0.93969262078590838405
#define D_SIN_S  0.34202014332566871291
#define D_NX     (-D_SIN_S)
#define D_NY     (D_COS_S)
#define D_THR    (-D_COS_S * 0.1)       // -cos(slope)*INIT_HEIGHT
#define D_EPS    1e-6
#define D_INVM   (1.0/(double)NV)

// ---------------- device state ----------------
__device__ double  g_I6[6];                  // sums: xx,yy,zz,xy,xz,yz of r=x-mc
__device__ double  g_inertia[9];             // body-frame inertia (row-major)
__device__ double  g_trans[3], g_quat[4], g_v[3], g_omega[3];
__device__ double  g_mc[3];
__device__ double  g_kn, g_mu, g_ld, g_ad;
__device__ float   g_AB[8];                  // Ax,Ay,Az,thrA, Bx,By,Bz,thrB
__device__ float   g_sum[3];
__device__ int     g_cnt;
__device__ unsigned g_arrive;
__device__ unsigned g_release;               // number of completed steps

// ---------------- small math helpers ----------------
__device__ __forceinline__ void quat_to_mat(const double* q, double R[3][3]) {
    double n = sqrt(q[0]*q[0] + q[1]*q[1] + q[2]*q[2] + q[3]*q[3]);
    double w = q[0]/n, x = q[1]/n, y = q[2]/n, z = q[3]/n;
    R[0][0] = 1.0 - 2.0*(y*y + z*z); R[0][1] = 2.0*(x*y - w*z);       R[0][2] = 2.0*(x*z + w*y);
    R[1][0] = 2.0*(x*y + w*z);       R[1][1] = 1.0 - 2.0*(x*x + z*z); R[1][2] = 2.0*(y*z - w*x);
    R[2][0] = 2.0*(x*z - w*y);       R[2][1] = 2.0*(y*z + w*x);       R[2][2] = 1.0 - 2.0*(x*x + y*y);
}

__device__ __forceinline__ void inv3(const double m[3][3], double o[3][3]) {
    double c00 = m[1][1]*m[2][2] - m[1][2]*m[2][1];
    double c01 = m[1][2]*m[2][0] - m[1][0]*m[2][2];
    double c02 = m[1][0]*m[2][1] - m[1][1]*m[2][0];
    double det = m[0][0]*c00 + m[0][1]*c01 + m[0][2]*c02;
    double id = 1.0/det;
    o[0][0] = c00*id;
    o[0][1] = (m[0][2]*m[2][1] - m[0][1]*m[2][2])*id;
    o[0][2] = (m[0][1]*m[1][2] - m[0][2]*m[1][1])*id;
    o[1][0] = c01*id;
    o[1][1] = (m[0][0]*m[2][2] - m[0][2]*m[2][0])*id;
    o[1][2] = (m[0][2]*m[1][0] - m[0][0]*m[1][2])*id;
    o[2][0] = c02*id;
    o[2][1] = (m[0][1]*m[2][0] - m[0][0]*m[2][1])*id;
    o[2][2] = (m[0][0]*m[1][1] - m[0][1]*m[1][0])*id;
}

__device__ __forceinline__ void mm3(const double a[3][3], const double b[3][3], double c[3][3]) {
    #pragma unroll
    for (int i = 0; i < 3; i++)
        #pragma unroll
        for (int j = 0; j < 3; j++)
            c[i][j] = a[i][0]*b[0][j] + a[i][1]*b[1][j] + a[i][2]*b[2][j];
}

// per-step reduction constants from current state
__device__ void compute_constants() {
    double R[3][3];
    quat_to_mat(g_quat, R);
    // A = R^T n  (n = (NX, NY, 0))
    double Ax = R[0][0]*D_NX + R[1][0]*D_NY;
    double Ay = R[0][1]*D_NX + R[1][1]*D_NY;
    double Az = R[0][2]*D_NX + R[1][2]*D_NY;
    double thrA = D_THR - ((g_trans[0] + g_mc[0])*D_NX + (g_trans[1] + g_mc[1])*D_NY);
    // n x omega
    double wx = g_omega[0], wy = g_omega[1], wz = g_omega[2];
    double cx =  D_NY*wz;
    double cy = -D_NX*wz;
    double cz =  D_NX*wy - D_NY*wx;
    double Bx = R[0][0]*cx + R[1][0]*cy + R[2][0]*cz;
    double By = R[0][1]*cx + R[1][1]*cy + R[2][1]*cz;
    double Bz = R[0][2]*cx + R[1][2]*cy + R[2][2]*cz;
    double thrB = -(g_v[0]*D_NX + g_v[1]*D_NY);
    g_AB[0] = (float)Ax; g_AB[1] = (float)Ay; g_AB[2] = (float)Az; g_AB[3] = (float)thrA;
    g_AB[4] = (float)Bx; g_AB[5] = (float)By; g_AB[6] = (float)Bz; g_AB[7] = (float)thrB;
}

// ---------------- kernels ----------------
__global__ void zero_kernel() {
    if (threadIdx.x == 0) {
        #pragma unroll
        for (int i = 0; i < 6; i++) g_I6[i] = 0.0;
        g_sum[0] = g_sum[1] = g_sum[2] = 0.0f;
        g_cnt = 0;
        g_arrive = 0u;
        g_release = 0u;
    }
}

__global__ void inertia_kernel(const float* __restrict__ x, const float* __restrict__ mc) {
    double mcx = mc[0], mcy = mc[1], mcz = mc[2];
    double s[6] = {0, 0, 0, 0, 0, 0};
    const float4* p = (const float4*)x;
    for (int g = blockIdx.x*blockDim.x + threadIdx.x; g < NGROUPS; g += gridDim.x*blockDim.x) {
        float4 f0 = p[3*g], f1 = p[3*g + 1], f2 = p[3*g + 2];
        double vx, vy, vz;
        #define ACC(a,b,c) { vx = (double)(a)-mcx; vy = (double)(b)-mcy; vz = (double)(c)-mcz; \
            s[0] += vx*vx; s[1] += vy*vy; s[2] += vz*vz; s[3] += vx*vy; s[4] += vx*vz; s[5] += vy*vz; }
        ACC(f0.x, f0.y, f0.z)
        ACC(f0.w, f1.x, f1.y)
        ACC(f1.z, f1.w, f2.x)
        ACC(f2.y, f2.z, f2.w)
        #undef ACC
    }
    #pragma unroll
    for (int o = 16; o; o >>= 1)
        #pragma unroll
        for (int i = 0; i < 6; i++) s[i] += __shfl_down_sync(0xffffffffu, s[i], o);
    __shared__ double sm[6][BLOCK/32];
    int lane = threadIdx.x & 31, w = threadIdx.x >> 5;
    if (lane == 0)
        #pragma unroll
        for (int i = 0; i < 6; i++) sm[i][w] = s[i];
    __syncthreads();
    if (threadIdx.x == 0) {
        #pragma unroll
        for (int i = 0; i < 6; i++) {
            double t = 0;
            #pragma unroll
            for (int j = 0; j < BLOCK/32; j++) t += sm[i][j];
            atomicAdd(&g_I6[i], t);
        }
    }
}

__global__ void init_kernel(const float* mc, const float* it, const float* iq,
                            const float* iv, const float* kn, const float* mu,
                            const float* ld, const float* ad) {
    double xx = g_I6[0], yy = g_I6[1], zz = g_I6[2];
    double xy = g_I6[3], xz = g_I6[4], yz = g_I6[5];
    double tr = xx + yy + zz;
    g_inertia[0] = tr - xx; g_inertia[4] = tr - yy; g_inertia[8] = tr - zz;
    g_inertia[1] = -xy; g_inertia[3] = -xy;
    g_inertia[2] = -xz; g_inertia[6] = -xz;
    g_inertia[5] = -yz; g_inertia[7] = -yz;
    for (int i = 0; i < 3; i++) {
        g_mc[i]    = (double)mc[i];
        g_trans[i] = (double)it[i];
        g_v[i]     = (double)iv[i];
        g_omega[i] = 0.0;
    }
    double q0 = iq[0], q1 = iq[1], q2 = iq[2], q3 = iq[3];
    double qn = sqrt(q0*q0 + q1*q1 + q2*q2 + q3*q3);
    g_quat[0] = q0/qn; g_quat[1] = q1/qn; g_quat[2] = q2/qn; g_quat[3] = q3/qn;
    g_kn = (double)kn[0]; g_mu = (double)mu[0];
    g_ld = (double)ld[0]; g_ad = (double)ad[0];
    g_sum[0] = g_sum[1] = g_sum[2] = 0.0f;
    g_cnt = 0;
    g_arrive = 0u;
    g_release = 0u;
    compute_constants();
}

__device__ __noinline__ void do_update(int t, float* __restrict__ out) {
    int num  = atomicAdd(&g_cnt, 0);
    double s0 = (double)atomicAdd(&g_sum[0], 0.0f);
    double s1 = (double)atomicAdd(&g_sum[1], 0.0f);
    double s2 = (double)atomicAdd(&g_sum[2], 0.0f);

    double numf = (num > 0) ? (double)num : 1.0;
    double ri0 = s0/numf, ri1 = s1/numf, ri2 = s2/numf;

    double R[3][3];
    quat_to_mat(g_quat, R);
    double Ri0 = R[0][0]*ri0 + R[0][1]*ri1 + R[0][2]*ri2;
    double Ri1 = R[1][0]*ri0 + R[1][1]*ri1 + R[1][2]*ri2;
    double Ri2 = R[2][0]*ri0 + R[2][1]*ri1 + R[2][2]*ri2;

    double vx = g_v[0], vy = g_v[1], vz = g_v[2];
    double wx = g_omega[0], wy = g_omega[1], wz = g_omega[2];

    // vi = v + omega x Ri
    double vix = vx + (wy*Ri2 - wz*Ri1);
    double viy = vy + (wz*Ri0 - wx*Ri2);
    double viz = vz + (wx*Ri1 - wy*Ri0);

    double vns = vix*D_NX + viy*D_NY;         // n.z == 0
    double vnx = vns*D_NX, vny = vns*D_NY;    // v_n
    double vtx = vix - vnx, vty = viy - vny, vtz = viz;
    double nvn = fabs(vns);
    double nvt = sqrt(vtx*vtx + vty*vty + vtz*vtz);
    double alpha = 1.0 - g_mu*(1.0 + g_kn)*(nvn/(nvt + D_EPS));
    if (alpha < 0.0) alpha = 0.0;
    // rhs = vi_new - vi, vi_new = -kn*v_n + alpha*v_t
    double rx = (-g_kn*vnx + alpha*vtx) - vix;
    double ry = (-g_kn*vny + alpha*vty) - viy;
    double rz = (          alpha*vtz) - viz;

    // I = R * inertia * R^T
    double In[3][3] = {{g_inertia[0], g_inertia[1], g_inertia[2]},
                       {g_inertia[3], g_inertia[4], g_inertia[5]},
                       {g_inertia[6], g_inertia[7], g_inertia[8]}};
    double Tm[3][3], Rt[3][3], Iw[3][3];
    mm3(R, In, Tm);
    #pragma unroll
    for (int i = 0; i < 3; i++)
        #pragma unroll
        for (int j = 0; j < 3; j++) Rt[i][j] = R[j][i];
    mm3(Tm, Rt, Iw);
    double Iinv[3][3];
    inv3(Iw, Iinv);

    double C[3][3] = {{0.0, -Ri2, Ri1}, {Ri2, 0.0, -Ri0}, {-Ri1, Ri0, 0.0}};
    double U[3][3], M[3][3];
    mm3(C, Iinv, U);
    mm3(U, C, M);
    double K[3][3];
    #pragma unroll
    for (int i = 0; i < 3; i++)
        #pragma unroll
        for (int j = 0; j < 3; j++) K[i][j] = ((i == j) ? D_INVM : 0.0) - M[i][j];
    double Kinv[3][3];
    inv3(K, Kinv);

    double Jx = Kinv[0][0]*rx + Kinv[0][1]*ry + Kinv[0][2]*rz;
    double Jy = Kinv[1][0]*rx + Kinv[1][1]*ry + Kinv[1][2]*rz;
    double Jz = Kinv[2][0]*rx + Kinv[2][1]*ry + Kinv[2][2]*rz;

    bool hit = (num > 0);
    double dvx = hit ? Jx*D_INVM : 0.0;
    double dvy = hit ? Jy*D_INVM : 0.0;
    double dvz = hit ? Jz*D_INVM : 0.0;
    // C*J = Ri x J
    double cjx = Ri1*Jz - Ri2*Jy;
    double cjy = Ri2*Jx - Ri0*Jz;
    double cjz = Ri0*Jy - Ri1*Jx;
    double dwx = hit ? (Iinv[0][0]*cjx + Iinv[0][1]*cjy + Iinv[0][2]*cjz) : 0.0;
    double dwy = hit ? (Iinv[1][0]*cjx + Iinv[1][1]*cjy + Iinv[1][2]*cjz) : 0.0;
    double dwz = hit ? (Iinv[2][0]*cjx + Iinv[2][1]*cjy + Iinv[2][2]*cjz) : 0.0;

    vx = vx*g_ld + dvx;
    vy = (vy - 9.8*D_DT)*g_ld + dvy;
    vz = vz*g_ld + dvz;
    wx = wx*g_ad + dwx;
    wy = wy*g_ad + dwy;
    wz = wz*g_ad + dwz;

    double tx = g_trans[0] + D_DT*vx;
    double ty = g_trans[1] + D_DT*vy;
    double tz = g_trans[2] + D_DT*vz;

    double h = 0.5*D_DT;
    double x1 = wx*h, y1 = wy*h, z1 = wz*h;
    double qw = g_quat[0], qx = g_quat[1], qy = g_quat[2], qz = g_quat[3];
    double nqw = qw + (-x1*qx - y1*qy - z1*qz);
    double nqx = qx + ( x1*qw + y1*qz - z1*qy);
    double nqy = qy + ( y1*qw + z1*qx - x1*qz);
    double nqz = qz + ( z1*qw + x1*qy - y1*qx);
    double qn = sqrt(nqw*nqw + nqx*nqx + nqy*nqy + nqz*nqz);
    nqw /= qn; nqx /= qn; nqy /= qn; nqz /= qn;

    g_trans[0] = tx; g_trans[1] = ty; g_trans[2] = tz;
    g_quat[0] = nqw; g_quat[1] = nqx; g_quat[2] = nqy; g_quat[3] = nqz;
    g_v[0] = vx; g_v[1] = vy; g_v[2] = vz;
    g_omega[0] = wx; g_omega[1] = wy; g_omega[2] = wz;

    out[7*t + 0] = (float)tx;
    out[7*t + 1] = (float)ty;
    out[7*t + 2] = (float)tz;
    out[7*t + 3] = (float)nqw;
    out[7*t + 4] = (float)nqx;
    out[7*t + 5] = (float)nqy;
    out[7*t + 6] = (float)nqz;

    // reset accumulators for next step; compute next-step constants
    g_sum[0] = g_sum[1] = g_sum[2] = 0.0f;
    g_cnt = 0;
    compute_constants();
}

// Persistent kernel: all TSTEPS steps inside one launch.
__global__ void __launch_bounds__(BLOCK, 2) persist_kernel(const float* __restrict__ x,
                                                           float* __restrict__ out) {
    const float4* p = (const float4*)x;
    volatile float* vAB = (volatile float*)g_AB;
    volatile unsigned* vrel = (volatile unsigned*)&g_release;

    for (int t = 0; t < TSTEPS; t++) {
        // read per-step constants (L1-bypassing: updated by another SM)
        float Ax = vAB[0], Ay = vAB[1], Az = vAB[2], thrA = vAB[3];
        float Bx = vAB[4], By = vAB[5], Bz = vAB[6], thrB = vAB[7];

        float sx = 0.0f, sy = 0.0f, sz = 0.0f;
        int c = 0;

        for (int g = blockIdx.x*BLOCK + threadIdx.x; g < NGROUPS; g += NBP*BLOCK) {
            float4 f0 = p[3*g], f1 = p[3*g + 1], f2 = p[3*g + 2];
            #define PROC(a,b,cc) { float pa = (a)*Ax + (b)*Ay + (cc)*Az; \
                                   float pb = (a)*Bx + (b)*By + (cc)*Bz; \
                                   if (pa < thrA && pb < thrB) { c++; sx += (a); sy += (b); sz += (cc); } }
            PROC(f0.x, f0.y, f0.z)
            PROC(f0.w, f1.x, f1.y)
            PROC(f1.z, f1.w, f2.x)
            PROC(f2.y, f2.z, f2.w)
            #undef PROC
        }

        // warp reduce
        #pragma unroll
        for (int o = 16; o; o >>= 1) {
            sx += __shfl_down_sync(0xffffffffu, sx, o);
            sy += __shfl_down_sync(0xffffffffu, sy, o);
            sz += __shfl_down_sync(0xffffffffu, sz, o);
            c  += __shfl_down_sync(0xffffffffu, c,  o);
        }
        __shared__ float ssx[BLOCK/32], ssy[BLOCK/32], ssz[BLOCK/32];
        __shared__ int   sc[BLOCK/32];
        int lane = threadIdx.x & 31, w = threadIdx.x >> 5;
        if (lane == 0) { ssx[w] = sx; ssy[w] = sy; ssz[w] = sz; sc[w] = c; }
        __syncthreads();

        if (threadIdx.x == 0) {
            float bx = 0, by = 0, bz = 0; int bc = 0;
            #pragma unroll
            for (int j = 0; j < BLOCK/32; j++) { bx += ssx[j]; by += ssy[j]; bz += ssz[j]; bc += sc[j]; }
            if (bc) {
                atomicAdd(&g_sum[0], bx);
                atomicAdd(&g_sum[1], by);
                atomicAdd(&g_sum[2], bz);
                atomicAdd(&g_cnt, bc);
            }
            __threadfence();
            unsigned tk = atomicAdd(&g_arrive, 1u);
            if (tk == NBP - 1u) {
                // last block: serial state update
                do_update(t, out);
                g_arrive = 0u;
                __threadfence();
                *vrel = (unsigned)(t + 1);
            } else {
                while (*vrel <= (unsigned)t) { __nanosleep(64); }
            }
            __threadfence();   // acquire: order constant reads after release read
        }
        __syncthreads();
    }
}

extern "C" void kernel_launch(void* const* d_in, const int* in_sizes, int n_in,
                              void* d_out, int out_size) {
    const float* x  = (const float*)d_in[0];
    const float* mc = (const float*)d_in[1];
    const float* it = (const float*)d_in[2];
    const float* iq = (const float*)d_in[3];
    const float* iv = (const float*)d_in[4];
    const float* kn = (const float*)d_in[5];
    const float* mu = (const float*)d_in[6];
    const float* ld = (const float*)d_in[7];
    const float* ad = (const float*)d_in[8];
    float* out = (float*)d_out;

    zero_kernel<<<1, 32>>>();
    inertia_kernel<<<1184, BLOCK>>>(x, mc);
    init_kernel<<<1, 1>>>(mc, it, iq, iv, kn, mu, ld, ad);
    persist_kernel<<<NBP, BLOCK>>>(x, out);
}

// round 3
// speedup vs baseline: 3.0133x; 2.4534x over previous
#include <cuda_runtime.h>
#include <math.h>

#define NV       2000000
#define NGROUPS  (NV/4)                 // 500000 groups of 4 vertices
#define BLOCK    256
#define NBP      296                    // persistent grid: 2 blocks/SM x 148 SMs
#define TSTEPS   240
#define STRIDE   (NBP*BLOCK)

#define F_DT     (1.0f/600.0f)
#define F_NX     (-0.34202014332566871291f)
#define F_NY     ( 0.93969262078590838405f)
#define F_THR    (-0.093969262078590838405f)   // -cos(slope)*0.1
#define F_EPS    1e-6f
#define F_INVM   (1.0f/2000000.0f)

// ---------------- device state ----------------
__device__ double  g_I6[6];              // fp64 sums: xx,yy,zz,xy,xz,yz
__device__ float   g_If[9];              // body-frame inertia (fp32, row-major)
__device__ float   g_S[13];              // trans[0..2], quat[3..6], v[7..9], omega[10..12]
__device__ float   g_mcf[3];
__device__ float   g_kn, g_mu, g_ld, g_ad;
__device__ float   g_AB[8];              // Ax,Ay,Az,thrA, Bx,By,Bz,thrB
__device__ float   g_sum[3];
__device__ int     g_cnt;
__device__ unsigned g_arrive;
__device__ unsigned g_release;           // number of completed steps

// ---------------- fp32 small math ----------------
__device__ __forceinline__ void quat_to_mat_f(float qw, float qx, float qy, float qz, float R[3][3]) {
    float n2 = qw*qw + qx*qx + qy*qy + qz*qz;
    float inv = 1.0f / sqrtf(n2);
    float w = qw*inv, x = qx*inv, y = qy*inv, z = qz*inv;
    R[0][0] = 1.0f - 2.0f*(y*y + z*z); R[0][1] = 2.0f*(x*y - w*z);        R[0][2] = 2.0f*(x*z + w*y);
    R[1][0] = 2.0f*(x*y + w*z);        R[1][1] = 1.0f - 2.0f*(x*x + z*z); R[1][2] = 2.0f*(y*z - w*x);
    R[2][0] = 2.0f*(x*z - w*y);        R[2][1] = 2.0f*(y*z + w*x);        R[2][2] = 1.0f - 2.0f*(x*x + y*y);
}

__device__ __forceinline__ void inv3f(const float m[3][3], float o[3][3]) {
    float c00 = m[1][1]*m[2][2] - m[1][2]*m[2][1];
    float c01 = m[1][2]*m[2][0] - m[1][0]*m[2][2];
    float c02 = m[1][0]*m[2][1] - m[1][1]*m[2][0];
    float det = m[0][0]*c00 + m[0][1]*c01 + m[0][2]*c02;
    float id = 1.0f/det;
    o[0][0] = c00*id;
    o[0][1] = (m[0][2]*m[2][1] - m[0][1]*m[2][2])*id;
    o[0][2] = (m[0][1]*m[1][2] - m[0][2]*m[1][1])*id;
    o[1][0] = c01*id;
    o[1][1] = (m[0][0]*m[2][2] - m[0][2]*m[2][0])*id;
    o[1][2] = (m[0][2]*m[1][0] - m[0][0]*m[1][2])*id;
    o[2][0] = c02*id;
    o[2][1] = (m[0][1]*m[2][0] - m[0][0]*m[2][1])*id;
    o[2][2] = (m[0][0]*m[1][1] - m[0][1]*m[1][0])*id;
}

__device__ __forceinline__ void mm3f(const float a[3][3], const float b[3][3], float c[3][3]) {
    #pragma unroll
    for (int i = 0; i < 3; i++)
        #pragma unroll
        for (int j = 0; j < 3; j++)
            c[i][j] = a[i][0]*b[0][j] + a[i][1]*b[1][j] + a[i][2]*b[2][j];
}

// per-step reduction constants from current state (volatile state reads)
__device__ void compute_constants() {
    volatile float* S = g_S;
    volatile float* AB = g_AB;
    float R[3][3];
    quat_to_mat_f(S[3], S[4], S[5], S[6], R);
    // A = R^T n
    float Ax = R[0][0]*F_NX + R[1][0]*F_NY;
    float Ay = R[0][1]*F_NX + R[1][1]*F_NY;
    float Az = R[0][2]*F_NX + R[1][2]*F_NY;
    float thrA = F_THR - ((S[0] + g_mcf[0])*F_NX + (S[1] + g_mcf[1])*F_NY);
    // B = R^T (n x omega)
    float wx = S[10], wy = S[11], wz = S[12];
    float cx =  F_NY*wz;
    float cy = -F_NX*wz;
    float cz =  F_NX*wy - F_NY*wx;
    float Bx = R[0][0]*cx + R[1][0]*cy + R[2][0]*cz;
    float By = R[0][1]*cx + R[1][1]*cy + R[2][1]*cz;
    float Bz = R[0][2]*cx + R[1][2]*cy + R[2][2]*cz;
    float thrB = -(S[7]*F_NX + S[8]*F_NY);
    AB[0] = Ax; AB[1] = Ay; AB[2] = Az; AB[3] = thrA;
    AB[4] = Bx; AB[5] = By; AB[6] = Bz; AB[7] = thrB;
}

// ---------------- kernels ----------------
__global__ void zero_kernel() {
    if (threadIdx.x == 0) {
        #pragma unroll
        for (int i = 0; i < 6; i++) g_I6[i] = 0.0;
        g_sum[0] = g_sum[1] = g_sum[2] = 0.0f;
        g_cnt = 0;
        g_arrive = 0u;
        g_release = 0u;
    }
}

__global__ void inertia_kernel(const float* __restrict__ x, const float* __restrict__ mc) {
    double mcx = mc[0], mcy = mc[1], mcz = mc[2];
    double s[6] = {0, 0, 0, 0, 0, 0};
    const float4* p = (const float4*)x;
    for (int g = blockIdx.x*blockDim.x + threadIdx.x; g < NGROUPS; g += gridDim.x*blockDim.x) {
        float4 f0 = p[3*g], f1 = p[3*g + 1], f2 = p[3*g + 2];
        double vx, vy, vz;
        #define ACC(a,b,c) { vx = (double)(a)-mcx; vy = (double)(b)-mcy; vz = (double)(c)-mcz; \
            s[0] += vx*vx; s[1] += vy*vy; s[2] += vz*vz; s[3] += vx*vy; s[4] += vx*vz; s[5] += vy*vz; }
        ACC(f0.x, f0.y, f0.z)
        ACC(f0.w, f1.x, f1.y)
        ACC(f1.z, f1.w, f2.x)
        ACC(f2.y, f2.z, f2.w)
        #undef ACC
    }
    #pragma unroll
    for (int o = 16; o; o >>= 1)
        #pragma unroll
        for (int i = 0; i < 6; i++) s[i] += __shfl_down_sync(0xffffffffu, s[i], o);
    __shared__ double sm[6][BLOCK/32];
    int lane = threadIdx.x & 31, w = threadIdx.x >> 5;
    if (lane == 0)
        #pragma unroll
        for (int i = 0; i < 6; i++) sm[i][w] = s[i];
    __syncthreads();
    if (threadIdx.x == 0) {
        #pragma unroll
        for (int i = 0; i < 6; i++) {
            double t = 0;
            #pragma unroll
            for (int j = 0; j < BLOCK/32; j++) t += sm[i][j];
            atomicAdd(&g_I6[i], t);
        }
    }
}

__global__ void init_kernel(const float* mc, const float* it, const float* iq,
                            const float* iv, const float* kn, const float* mu,
                            const float* ld, const float* ad) {
    double xx = g_I6[0], yy = g_I6[1], zz = g_I6[2];
    double xy = g_I6[3], xz = g_I6[4], yz = g_I6[5];
    double tr = xx + yy + zz;
    g_If[0] = (float)(tr - xx); g_If[4] = (float)(tr - yy); g_If[8] = (float)(tr - zz);
    g_If[1] = (float)(-xy); g_If[3] = (float)(-xy);
    g_If[2] = (float)(-xz); g_If[6] = (float)(-xz);
    g_If[5] = (float)(-yz); g_If[7] = (float)(-yz);
    volatile float* S = g_S;
    for (int i = 0; i < 3; i++) {
        g_mcf[i] = mc[i];
        S[i]     = it[i];      // trans
        S[7+i]   = iv[i];      // v
        S[10+i]  = 0.0f;       // omega
    }
    float q0 = iq[0], q1 = iq[1], q2 = iq[2], q3 = iq[3];
    float qi = 1.0f / sqrtf(q0*q0 + q1*q1 + q2*q2 + q3*q3);
    S[3] = q0*qi; S[4] = q1*qi; S[5] = q2*qi; S[6] = q3*qi;
    g_kn = kn[0]; g_mu = mu[0];
    g_ld = ld[0]; g_ad = ad[0];
    g_sum[0] = g_sum[1] = g_sum[2] = 0.0f;
    g_cnt = 0;
    g_arrive = 0u;
    g_release = 0u;
    compute_constants();
}

__device__ __noinline__ void do_update(int t, float* __restrict__ out) {
    volatile float* S = g_S;
    int num  = *(volatile int*)&g_cnt;
    volatile float* vs = g_sum;
    float s0 = vs[0], s1 = vs[1], s2 = vs[2];

    float numf = (num > 0) ? (float)num : 1.0f;
    float inumf = 1.0f / numf;
    float ri0 = s0*inumf, ri1 = s1*inumf, ri2 = s2*inumf;

    float qw = S[3], qx = S[4], qy = S[5], qz = S[6];
    float R[3][3];
    quat_to_mat_f(qw, qx, qy, qz, R);
    float Ri0 = R[0][0]*ri0 + R[0][1]*ri1 + R[0][2]*ri2;
    float Ri1 = R[1][0]*ri0 + R[1][1]*ri1 + R[1][2]*ri2;
    float Ri2 = R[2][0]*ri0 + R[2][1]*ri1 + R[2][2]*ri2;

    float vx = S[7], vy = S[8], vz = S[9];
    float wx = S[10], wy = S[11], wz = S[12];
    float knv = g_kn, muv = g_mu, ldv = g_ld, adv = g_ad;

    // vi = v + omega x Ri
    float vix = vx + (wy*Ri2 - wz*Ri1);
    float viy = vy + (wz*Ri0 - wx*Ri2);
    float viz = vz + (wx*Ri1 - wy*Ri0);

    float vns = vix*F_NX + viy*F_NY;           // n.z == 0
    float vnx = vns*F_NX, vny = vns*F_NY;      // v_n
    float vtx = vix - vnx, vty = viy - vny, vtz = viz;
    float nvn = fabsf(vns);
    float nvt = sqrtf(vtx*vtx + vty*vty + vtz*vtz);
    float alpha = 1.0f - muv*(1.0f + knv)*(nvn/(nvt + F_EPS));
    if (alpha < 0.0f) alpha = 0.0f;
    float rx = (-knv*vnx + alpha*vtx) - vix;
    float ry = (-knv*vny + alpha*vty) - viy;
    float rz = (           alpha*vtz) - viz;

    // I = R * inertia * R^T
    float In[3][3] = {{g_If[0], g_If[1], g_If[2]},
                      {g_If[3], g_If[4], g_If[5]},
                      {g_If[6], g_If[7], g_If[8]}};
    float Tm[3][3], Rt[3][3], Iw[3][3];
    mm3f(R, In, Tm);
    #pragma unroll
    for (int i = 0; i < 3; i++)
        #pragma unroll
        for (int j = 0; j < 3; j++) Rt[i][j] = R[j][i];
    mm3f(Tm, Rt, Iw);
    float Iinv[3][3];
    inv3f(Iw, Iinv);

    float C[3][3] = {{0.0f, -Ri2, Ri1}, {Ri2, 0.0f, -Ri0}, {-Ri1, Ri0, 0.0f}};
    float U[3][3], M[3][3];
    mm3f(C, Iinv, U);
    mm3f(U, C, M);
    float K[3][3];
    #pragma unroll
    for (int i = 0; i < 3; i++)
        #pragma unroll
        for (int j = 0; j < 3; j++) K[i][j] = ((i == j) ? F_INVM : 0.0f) - M[i][j];
    float Kinv[3][3];
    inv3f(K, Kinv);

    float Jx = Kinv[0][0]*rx + Kinv[0][1]*ry + Kinv[0][2]*rz;
    float Jy = Kinv[1][0]*rx + Kinv[1][1]*ry + Kinv[1][2]*rz;
    float Jz = Kinv[2][0]*rx + Kinv[2][1]*ry + Kinv[2][2]*rz;

    bool hit = (num > 0);
    float dvx = hit ? Jx*F_INVM : 0.0f;
    float dvy = hit ? Jy*F_INVM : 0.0f;
    float dvz = hit ? Jz*F_INVM : 0.0f;
    float cjx = Ri1*Jz - Ri2*Jy;
    float cjy = Ri2*Jx - Ri0*Jz;
    float cjz = Ri0*Jy - Ri1*Jx;
    float dwx = hit ? (Iinv[0][0]*cjx + Iinv[0][1]*cjy + Iinv[0][2]*cjz) : 0.0f;
    float dwy = hit ? (Iinv[1][0]*cjx + Iinv[1][1]*cjy + Iinv[1][2]*cjz) : 0.0f;
    float dwz = hit ? (Iinv[2][0]*cjx + Iinv[2][1]*cjy + Iinv[2][2]*cjz) : 0.0f;

    vx = vx*ldv + dvx;
    vy = (vy - 9.8f*F_DT)*ldv + dvy;
    vz = vz*ldv + dvz;
    wx = wx*adv + dwx;
    wy = wy*adv + dwy;
    wz = wz*adv + dwz;

    float tx = S[0] + F_DT*vx;
    float ty = S[1] + F_DT*vy;
    float tz = S[2] + F_DT*vz;

    float h = 0.5f*F_DT;
    float x1 = wx*h, y1 = wy*h, z1 = wz*h;
    float nqw = qw + (-x1*qx - y1*qy - z1*qz);
    float nqx = qx + ( x1*qw + y1*qz - z1*qy);
    float nqy = qy + ( y1*qw + z1*qx - x1*qz);
    float nqz = qz + ( z1*qw + x1*qy - y1*qx);
    float qni = 1.0f / sqrtf(nqw*nqw + nqx*nqx + nqy*nqy + nqz*nqz);
    nqw *= qni; nqx *= qni; nqy *= qni; nqz *= qni;

    S[0] = tx; S[1] = ty; S[2] = tz;
    S[3] = nqw; S[4] = nqx; S[5] = nqy; S[6] = nqz;
    S[7] = vx; S[8] = vy; S[9] = vz;
    S[10] = wx; S[11] = wy; S[12] = wz;

    out[7*t + 0] = tx;
    out[7*t + 1] = ty;
    out[7*t + 2] = tz;
    out[7*t + 3] = nqw;
    out[7*t + 4] = nqx;
    out[7*t + 5] = nqy;
    out[7*t + 6] = nqz;

    // reset accumulators for next step; publish next-step constants
    vs[0] = 0.0f; vs[1] = 0.0f; vs[2] = 0.0f;
    *(volatile int*)&g_cnt = 0;
    compute_constants();
}

// Persistent kernel: all TSTEPS steps inside one launch.
__global__ void __launch_bounds__(BLOCK, 2) persist_kernel(const float* __restrict__ x,
                                                           float* __restrict__ out) {
    const float4* p = (const float4*)x;
    volatile float* vAB = (volatile float*)g_AB;
    volatile unsigned* vrel = (volatile unsigned*)&g_release;
    const int base = blockIdx.x*BLOCK + threadIdx.x;

    for (int t = 0; t < TSTEPS; t++) {
        // per-step constants (L1-bypassing: written by another SM)
        float Ax = vAB[0], Ay = vAB[1], Az = vAB[2], thrA = vAB[3];
        float Bx = vAB[4], By = vAB[5], Bz = vAB[6], thrB = vAB[7];

        float sx = 0.0f, sy = 0.0f, sz = 0.0f;
        int c = 0;

        #define PROC(a,b,cc) { float pa = (a)*Ax + (b)*Ay + (cc)*Az; \
                               float pb = (a)*Bx + (b)*By + (cc)*Bz; \
                               if (pa < thrA && pb < thrB) { c++; sx += (a); sy += (b); sz += (cc); } }
        // unrolled x2 grid-stride: 6 independent LDG.128 in flight
        for (int g = base; g < NGROUPS; g += 2*STRIDE) {
            float4 a0 = p[3*g], a1 = p[3*g + 1], a2 = p[3*g + 2];
            int g2 = g + STRIDE;
            float4 b0, b1, b2;
            bool ok2 = (g2 < NGROUPS);
            if (ok2) { b0 = p[3*g2]; b1 = p[3*g2 + 1]; b2 = p[3*g2 + 2]; }
            PROC(a0.x, a0.y, a0.z)
            PROC(a0.w, a1.x, a1.y)
            PROC(a1.z, a1.w, a2.x)
            PROC(a2.y, a2.z, a2.w)
            if (ok2) {
                PROC(b0.x, b0.y, b0.z)
                PROC(b0.w, b1.x, b1.y)
                PROC(b1.z, b1.w, b2.x)
                PROC(b2.y, b2.z, b2.w)
            }
        }
        #undef PROC

        // warp reduce
        #pragma unroll
        for (int o = 16; o; o >>= 1) {
            sx += __shfl_down_sync(0xffffffffu, sx, o);
            sy += __shfl_down_sync(0xffffffffu, sy, o);
            sz += __shfl_down_sync(0xffffffffu, sz, o);
            c  += __shfl_down_sync(0xffffffffu, c,  o);
        }
        __shared__ float ssx[BLOCK/32], ssy[BLOCK/32], ssz[BLOCK/32];
        __shared__ int   sc[BLOCK/32];
        int lane = threadIdx.x & 31, w = threadIdx.x >> 5;
        if (lane == 0) { ssx[w] = sx; ssy[w] = sy; ssz[w] = sz; sc[w] = c; }
        __syncthreads();

        if (threadIdx.x == 0) {
            float bx = 0, by = 0, bz = 0; int bc = 0;
            #pragma unroll
            for (int j = 0; j < BLOCK/32; j++) { bx += ssx[j]; by += ssy[j]; bz += ssz[j]; bc += sc[j]; }
            if (bc) {
                atomicAdd(&g_sum[0], bx);
                atomicAdd(&g_sum[1], by);
                atomicAdd(&g_sum[2], bz);
                atomicAdd(&g_cnt, bc);
            }
            __threadfence();
            unsigned tk = atomicAdd(&g_arrive, 1u);
            if (tk == NBP - 1u) {
                // last block: serial state update (fp32)
                do_update(t, out);
                g_arrive = 0u;
                __threadfence();
                *vrel = (unsigned)(t + 1);
            } else {
                while (*vrel <= (unsigned)t) { __nanosleep(64); }
            }
            __threadfence();   // acquire: order constant reads after release read
        }
        __syncthreads();
    }
}

extern "C" void kernel_launch(void* const* d_in, const int* in_sizes, int n_in,
                              void* d_out, int out_size) {
    const float* x  = (const float*)d_in[0];
    const float* mc = (const float*)d_in[1];
    const float* it = (const float*)d_in[2];
    const float* iq = (const float*)d_in[3];
    const float* iv = (const float*)d_in[4];
    const float* kn = (const float*)d_in[5];
    const float* mu = (const float*)d_in[6];
    const float* ld = (const float*)d_in[7];
    const float* ad = (const float*)d_in[8];
    float* out = (float*)d_out;

    zero_kernel<<<1, 32>>>();
    inertia_kernel<<<1184, BLOCK>>>(x, mc);
    init_kernel<<<1, 1>>>(mc, it, iq, iv, kn, mu, ld, ad);
    persist_kernel<<<NBP, BLOCK>>>(x, out);
}